// round 2
// baseline (speedup 1.0000x reference)
#include <cuda_runtime.h>

// DeltaRuleUpdate: new_M = M + phi^T V - (phi^T phi) M ; new_z = z + colsum(phi)
// phi = elu(K)+1. Shapes: K,V (4,16,8192,128), M (4,16,128,128), z (4,16,128).

#define BB 4
#define HH 16
#define SS 8192
#define DK 128
#define DV 128
#define BH (BB*HH)
#define NS 8              // S-splits per (b,h)
#define SCHUNK (SS/NS)    // 1024
#define TS 32             // s-tile staged in smem
#define LDA 132           // padded smem row stride (floats)

// Scratch: [target(2)][bh][chunk][128*128] partials; fully rewritten every call.
__device__ float g_scr[2ull * BH * NS * DK * DV];
__device__ float g_zscr[(size_t)BH * NS * DK];

typedef unsigned long long u64;

__device__ __forceinline__ u64 pk2(float x, float y) {
    u64 r; asm("mov.b64 %0,{%1,%2};" : "=l"(r) : "f"(x), "f"(y)); return r;
}
__device__ __forceinline__ void fma2(u64 &c, u64 a, u64 b) {
    asm("fma.rn.f32x2 %0,%1,%2,%0;" : "+l"(c) : "l"(a), "l"(b));
}
__device__ __forceinline__ void add2(u64 &c, u64 a) {
    asm("add.rn.f32x2 %0,%1,%0;" : "+l"(c) : "l"(a));
}
__device__ __forceinline__ float phi_f(float x) {
    return x > 0.f ? x + 1.f : __expf(x);   // elu(x)+1
}

// ---------------------------------------------------------------------------
// Phase 1: per (chunk, bh, target) compute 128x128 partial:
//   target 0: G_part = phi_chunk^T phi_chunk  (+ z column sums)
//   target 1: A_part = phi_chunk^T V_chunk
// ---------------------------------------------------------------------------
__global__ __launch_bounds__(256, 2)
void drp1_kernel(const float* __restrict__ K, const float* __restrict__ V) {
    const int chunk = blockIdx.x;
    const int bh    = blockIdx.y;
    const int t     = blockIdx.z;

    __shared__ float shA[TS * LDA];   // phi tile
    __shared__ float shB[TS * LDA];   // V tile (target 1 only)

    const float* Kp = K + (size_t)bh * SS * DK + (size_t)chunk * SCHUNK * DK;
    const float* Vp = V + (size_t)bh * SS * DV + (size_t)chunk * SCHUNK * DV;

    const int tid = threadIdx.x;
    const int tx = tid & 15, ty = tid >> 4;
    const int ra = ty * 8, cb = tx * 8;
    const bool zflag = (t == 0) && (ty == 0);

    u64 acc[8][4];
    #pragma unroll
    for (int i = 0; i < 8; i++)
        #pragma unroll
        for (int p = 0; p < 4; p++) acc[i][p] = 0ull;
    u64 zacc[4] = {0ull, 0ull, 0ull, 0ull};

    const float* Bsh = (t == 1) ? shB : shA;

    for (int s0 = 0; s0 < SCHUNK; s0 += TS) {
        // Stage tile: 32 rows x 128 cols, float4 per thread x4
        #pragma unroll
        for (int r = 0; r < 4; r++) {
            int id  = tid + 256 * r;
            int row = id >> 5;
            int c   = (id & 31) * 4;
            float4 kv = *(const float4*)(Kp + (size_t)(s0 + row) * DK + c);
            kv.x = phi_f(kv.x); kv.y = phi_f(kv.y);
            kv.z = phi_f(kv.z); kv.w = phi_f(kv.w);
            *(float4*)(shA + row * LDA + c) = kv;
            if (t == 1) {
                float4 vv = *(const float4*)(Vp + (size_t)(s0 + row) * DV + c);
                *(float4*)(shB + row * LDA + c) = vv;
            }
        }
        __syncthreads();

        #pragma unroll 4
        for (int s = 0; s < TS; s++) {
            float4 a0 = *(const float4*)(shA + s * LDA + ra);
            float4 a1 = *(const float4*)(shA + s * LDA + ra + 4);
            ulonglong2 b01 = *(const ulonglong2*)(Bsh + s * LDA + cb);
            ulonglong2 b23 = *(const ulonglong2*)(Bsh + s * LDA + cb + 4);
            u64 b[4] = {b01.x, b01.y, b23.x, b23.y};
            float av[8] = {a0.x, a0.y, a0.z, a0.w, a1.x, a1.y, a1.z, a1.w};
            #pragma unroll
            for (int i = 0; i < 8; i++) {
                u64 pa = pk2(av[i], av[i]);
                #pragma unroll
                for (int p = 0; p < 4; p++) fma2(acc[i][p], pa, b[p]);
            }
            if (zflag) {
                #pragma unroll
                for (int p = 0; p < 4; p++) add2(zacc[p], b[p]);
            }
        }
        __syncthreads();
    }

    float* C = g_scr + ((size_t)(t * BH + bh) * NS + chunk) * (DK * DV);
    #pragma unroll
    for (int i = 0; i < 8; i++)
        #pragma unroll
        for (int p = 0; p < 4; p++)
            *(u64*)(C + (size_t)(ra + i) * DV + cb + 2 * p) = acc[i][p];

    if (zflag) {
        float* zp = g_zscr + ((size_t)bh * NS + chunk) * DK;
        #pragma unroll
        for (int p = 0; p < 4; p++) *(u64*)(zp + cb + 2 * p) = zacc[p];
    }
}

// ---------------------------------------------------------------------------
// Phase 2: per bh: acc = M + sum_c A_part[c]; acc -= (sum_c G_part[c]) * M;
//          new_z = z + sum_c z_part[c]
// ---------------------------------------------------------------------------
__global__ __launch_bounds__(256, 2)
void drp2_kernel(const float* __restrict__ M, const float* __restrict__ z,
                 float* __restrict__ out) {
    const int bh = blockIdx.x;
    __shared__ float GT[TS * LDA];    // transposed G slab: [kk][i]

    const int tid = threadIdx.x;
    const int tx = tid & 15, ty = tid >> 4;
    const int ra = ty * 8, cb = tx * 8;

    const float* Mp  = M + (size_t)bh * DK * DV;
    const float* Asc = g_scr + ((size_t)(BH + bh) * NS) * (DK * DV);
    const float* Gsc = g_scr + ((size_t)bh * NS) * (DK * DV);

    u64 acc[8][4];
    // init: M tile + reduced A tile
    #pragma unroll
    for (int i = 0; i < 8; i++) {
        #pragma unroll
        for (int p = 0; p < 4; p++) {
            float2 m = *(const float2*)(Mp + (size_t)(ra + i) * DV + cb + 2 * p);
            u64 a = pk2(m.x, m.y);
            #pragma unroll
            for (int c = 0; c < NS; c++)
                add2(a, *(const u64*)(Asc + (size_t)c * DK * DV +
                                      (size_t)(ra + i) * DV + cb + 2 * p));
            acc[i][p] = a;
        }
    }

    for (int ks = 0; ks < DK; ks += TS) {
        __syncthreads();   // protect GT writes vs previous slab's reads
        // reduce + transpose G slab into smem: element (i, k=ks+kk) -> GT[kk][i]
        for (int e = tid; e < DK * TS; e += 256) {
            int i  = e >> 5;       // 0..127
            int kk = e & 31;       // 0..31 (coalesced inner)
            float sum = 0.f;
            #pragma unroll
            for (int c = 0; c < NS; c++)
                sum += Gsc[(size_t)c * DK * DV + (size_t)i * DK + ks + kk];
            GT[kk * LDA + i] = sum;
        }
        __syncthreads();

        #pragma unroll 4
        for (int kk = 0; kk < TS; kk++) {
            int k = ks + kk;
            float4 a0 = *(const float4*)(GT + kk * LDA + ra);
            float4 a1 = *(const float4*)(GT + kk * LDA + ra + 4);
            float4 b0 = __ldg((const float4*)(Mp + (size_t)k * DV + cb));
            float4 b1 = __ldg((const float4*)(Mp + (size_t)k * DV + cb + 4));
            u64 b[4] = {pk2(b0.x, b0.y), pk2(b0.z, b0.w),
                        pk2(b1.x, b1.y), pk2(b1.z, b1.w)};
            float av[8] = {a0.x, a0.y, a0.z, a0.w, a1.x, a1.y, a1.z, a1.w};
            #pragma unroll
            for (int i = 0; i < 8; i++) {
                u64 pa = pk2(-av[i], -av[i]);
                #pragma unroll
                for (int p = 0; p < 4; p++) fma2(acc[i][p], pa, b[p]);
            }
        }
    }

    float* outM = out + (size_t)bh * DK * DV;
    #pragma unroll
    for (int i = 0; i < 8; i++)
        #pragma unroll
        for (int p = 0; p < 4; p++)
            *(u64*)(outM + (size_t)(ra + i) * DV + cb + 2 * p) = acc[i][p];

    if (tid < DK) {
        float s = z[(size_t)bh * DK + tid];
        #pragma unroll
        for (int c = 0; c < NS; c++)
            s += g_zscr[((size_t)bh * NS + c) * DK + tid];
        out[(size_t)BH * DK * DV + (size_t)bh * DK + tid] = s;
    }
}

extern "C" void kernel_launch(void* const* d_in, const int* in_sizes, int n_in,
                              void* d_out, int out_size) {
    const float* K = (const float*)d_in[0];
    const float* V = (const float*)d_in[1];
    const float* M = (const float*)d_in[2];
    const float* z = (const float*)d_in[3];
    float* out = (float*)d_out;

    dim3 g1(NS, BH, 2);
    drp1_kernel<<<g1, 256>>>(K, V);
    drp2_kernel<<<BH, 256>>>(M, z, out);
}

// round 3
// speedup vs baseline: 1.0037x; 1.0037x over previous
#include <cuda_runtime.h>

// DeltaRuleUpdate: new_M = M + phi^T V - (phi^T phi) M ; new_z = z + colsum(phi)
// phi = elu(K)+1. Shapes: K,V (4,16,8192,128), M (4,16,128,128), z (4,16,128).

#define BB 4
#define HH 16
#define SS 8192
#define DK 128
#define DV 128
#define BH (BB*HH)
#define NS 8              // S-splits per (b,h)
#define SCHUNK (SS/NS)    // 1024
#define TS 32             // s-tile staged in smem
#define LDA 132           // padded smem row stride (floats)

// Scratch: [target(2)][bh][chunk][128*128] partials; fully rewritten every call.
__device__ float g_scr[2ull * BH * NS * DK * DV];
__device__ float g_zscr[(size_t)BH * NS * DK];

typedef unsigned long long u64;

__device__ __forceinline__ u64 pk2(float x, float y) {
    u64 r; asm("mov.b64 %0,{%1,%2};" : "=l"(r) : "f"(x), "f"(y)); return r;
}
__device__ __forceinline__ void fma2(u64 &c, u64 a, u64 b) {
    asm("fma.rn.f32x2 %0,%1,%2,%0;" : "+l"(c) : "l"(a), "l"(b));
}
__device__ __forceinline__ void add2(u64 &c, u64 a) {
    asm("add.rn.f32x2 %0,%1,%0;" : "+l"(c) : "l"(a));
}
__device__ __forceinline__ float phi_f(float x) {
    return x > 0.f ? x + 1.f : __expf(x);   // elu(x)+1
}

// ---------------------------------------------------------------------------
// Phase 1: per (chunk, bh, target) compute 128x128 partial:
//   target 0: G_part = phi_chunk^T phi_chunk  (+ z column sums)
//   target 1: A_part = phi_chunk^T V_chunk
// ---------------------------------------------------------------------------
__global__ __launch_bounds__(256, 2)
void drp1_kernel(const float* __restrict__ K, const float* __restrict__ V) {
    const int chunk = blockIdx.x;
    const int bh    = blockIdx.y;
    const int t     = blockIdx.z;

    __shared__ float shA[TS * LDA];   // phi tile
    __shared__ float shB[TS * LDA];   // V tile (target 1 only)

    const float* Kp = K + (size_t)bh * SS * DK + (size_t)chunk * SCHUNK * DK;
    const float* Vp = V + (size_t)bh * SS * DV + (size_t)chunk * SCHUNK * DV;

    const int tid = threadIdx.x;
    const int tx = tid & 15, ty = tid >> 4;
    const int ra = ty * 8, cb = tx * 8;
    const bool zflag = (t == 0) && (ty == 0);

    u64 acc[8][4];
    #pragma unroll
    for (int i = 0; i < 8; i++)
        #pragma unroll
        for (int p = 0; p < 4; p++) acc[i][p] = 0ull;
    u64 zacc[4] = {0ull, 0ull, 0ull, 0ull};

    const float* Bsh = (t == 1) ? shB : shA;

    for (int s0 = 0; s0 < SCHUNK; s0 += TS) {
        // Stage tile: 32 rows x 128 cols, float4 per thread x4
        #pragma unroll
        for (int r = 0; r < 4; r++) {
            int id  = tid + 256 * r;
            int row = id >> 5;
            int c   = (id & 31) * 4;
            float4 kv = *(const float4*)(Kp + (size_t)(s0 + row) * DK + c);
            kv.x = phi_f(kv.x); kv.y = phi_f(kv.y);
            kv.z = phi_f(kv.z); kv.w = phi_f(kv.w);
            *(float4*)(shA + row * LDA + c) = kv;
            if (t == 1) {
                float4 vv = *(const float4*)(Vp + (size_t)(s0 + row) * DV + c);
                *(float4*)(shB + row * LDA + c) = vv;
            }
        }
        __syncthreads();

        #pragma unroll 4
        for (int s = 0; s < TS; s++) {
            float4 a0 = *(const float4*)(shA + s * LDA + ra);
            float4 a1 = *(const float4*)(shA + s * LDA + ra + 4);
            ulonglong2 b01 = *(const ulonglong2*)(Bsh + s * LDA + cb);
            ulonglong2 b23 = *(const ulonglong2*)(Bsh + s * LDA + cb + 4);
            u64 b[4] = {b01.x, b01.y, b23.x, b23.y};
            float av[8] = {a0.x, a0.y, a0.z, a0.w, a1.x, a1.y, a1.z, a1.w};
            #pragma unroll
            for (int i = 0; i < 8; i++) {
                u64 pa = pk2(av[i], av[i]);
                #pragma unroll
                for (int p = 0; p < 4; p++) fma2(acc[i][p], pa, b[p]);
            }
            if (zflag) {
                #pragma unroll
                for (int p = 0; p < 4; p++) add2(zacc[p], b[p]);
            }
        }
        __syncthreads();
    }

    float* C = g_scr + ((size_t)(t * BH + bh) * NS + chunk) * (DK * DV);
    #pragma unroll
    for (int i = 0; i < 8; i++)
        #pragma unroll
        for (int p = 0; p < 4; p++)
            *(u64*)(C + (size_t)(ra + i) * DV + cb + 2 * p) = acc[i][p];

    if (zflag) {
        float* zp = g_zscr + ((size_t)bh * NS + chunk) * DK;
        #pragma unroll
        for (int p = 0; p < 4; p++) *(u64*)(zp + cb + 2 * p) = zacc[p];
    }
}

// ---------------------------------------------------------------------------
// Phase 2: per bh: acc = M + sum_c A_part[c]; acc -= (sum_c G_part[c]) * M;
//          new_z = z + sum_c z_part[c]
// ---------------------------------------------------------------------------
__global__ __launch_bounds__(256, 2)
void drp2_kernel(const float* __restrict__ M, const float* __restrict__ z,
                 float* __restrict__ out) {
    const int bh = blockIdx.x;
    __shared__ float GT[TS * LDA];    // transposed G slab: [kk][i]

    const int tid = threadIdx.x;
    const int tx = tid & 15, ty = tid >> 4;
    const int ra = ty * 8, cb = tx * 8;

    const float* Mp  = M + (size_t)bh * DK * DV;
    const float* Asc = g_scr + ((size_t)(BH + bh) * NS) * (DK * DV);
    const float* Gsc = g_scr + ((size_t)bh * NS) * (DK * DV);

    u64 acc[8][4];
    // init: M tile + reduced A tile
    #pragma unroll
    for (int i = 0; i < 8; i++) {
        #pragma unroll
        for (int p = 0; p < 4; p++) {
            float2 m = *(const float2*)(Mp + (size_t)(ra + i) * DV + cb + 2 * p);
            u64 a = pk2(m.x, m.y);
            #pragma unroll
            for (int c = 0; c < NS; c++)
                add2(a, *(const u64*)(Asc + (size_t)c * DK * DV +
                                      (size_t)(ra + i) * DV + cb + 2 * p));
            acc[i][p] = a;
        }
    }

    for (int ks = 0; ks < DK; ks += TS) {
        __syncthreads();   // protect GT writes vs previous slab's reads
        // reduce + transpose G slab into smem: element (i, k=ks+kk) -> GT[kk][i]
        for (int e = tid; e < DK * TS; e += 256) {
            int i  = e >> 5;       // 0..127
            int kk = e & 31;       // 0..31 (coalesced inner)
            float sum = 0.f;
            #pragma unroll
            for (int c = 0; c < NS; c++)
                sum += Gsc[(size_t)c * DK * DV + (size_t)i * DK + ks + kk];
            GT[kk * LDA + i] = sum;
        }
        __syncthreads();

        #pragma unroll 4
        for (int kk = 0; kk < TS; kk++) {
            int k = ks + kk;
            float4 a0 = *(const float4*)(GT + kk * LDA + ra);
            float4 a1 = *(const float4*)(GT + kk * LDA + ra + 4);
            float4 b0 = __ldg((const float4*)(Mp + (size_t)k * DV + cb));
            float4 b1 = __ldg((const float4*)(Mp + (size_t)k * DV + cb + 4));
            u64 b[4] = {pk2(b0.x, b0.y), pk2(b0.z, b0.w),
                        pk2(b1.x, b1.y), pk2(b1.z, b1.w)};
            float av[8] = {a0.x, a0.y, a0.z, a0.w, a1.x, a1.y, a1.z, a1.w};
            #pragma unroll
            for (int i = 0; i < 8; i++) {
                u64 pa = pk2(-av[i], -av[i]);
                #pragma unroll
                for (int p = 0; p < 4; p++) fma2(acc[i][p], pa, b[p]);
            }
        }
    }

    float* outM = out + (size_t)bh * DK * DV;
    #pragma unroll
    for (int i = 0; i < 8; i++)
        #pragma unroll
        for (int p = 0; p < 4; p++)
            *(u64*)(outM + (size_t)(ra + i) * DV + cb + 2 * p) = acc[i][p];

    if (tid < DK) {
        float s = z[(size_t)bh * DK + tid];
        #pragma unroll
        for (int c = 0; c < NS; c++)
            s += g_zscr[((size_t)bh * NS + c) * DK + tid];
        out[(size_t)BH * DK * DV + (size_t)bh * DK + tid] = s;
    }
}

extern "C" void kernel_launch(void* const* d_in, const int* in_sizes, int n_in,
                              void* d_out, int out_size) {
    const float* K = (const float*)d_in[0];
    const float* V = (const float*)d_in[1];
    const float* M = (const float*)d_in[2];
    const float* z = (const float*)d_in[3];
    float* out = (float*)d_out;

    dim3 g1(NS, BH, 2);
    drp1_kernel<<<g1, 256>>>(K, V);
    drp2_kernel<<<BH, 256>>>(M, z, out);
}

// round 5
// speedup vs baseline: 1.7750x; 1.7685x over previous
#include <cuda_runtime.h>
#include <cuda_bf16.h>
#include <cstdint>

// new_M = M + phi^T V - (phi^T phi) M ; new_z = z + colsum(phi); phi = elu(K)+1
// K,V: (64, 8192, 128) fp32 flattened over (b,h).
// Phase1: warp-level bf16 mma.sync (HMMA), hi/lo split on phi for G accuracy.
//   Gp = HI^T HI + HI^T (2 LO)  -> phase2 symmetrizes: G = (Gp + Gp^T)/2
//   A  = HI^T V(bf16)
// Phase2: reduce partials, symmetrize, new_M = M + A - G*M, new_z.

#define SS 8192
#define NBH 64
#define NS 4                 // S-splits per (bh, target)
#define SR (SS / NS)         // 2048
#define KC 32                // s per staged chunk
#define NCH (SR / KC)        // 64

__device__ float g_G[(size_t)NBH * NS * 128 * 128];   // Gp partials
__device__ float g_A[(size_t)NBH * NS * 128 * 128];   // A partials
__device__ float g_z[(size_t)NBH * NS * 2 * 128];     // z partials

typedef unsigned long long u64;

// ---------------- helpers ----------------
__device__ __forceinline__ uint32_t smem_u32(const void* p) {
    uint32_t a;
    asm("{ .reg .u64 t; cvta.to.shared.u64 t, %1; cvt.u32.u64 %0, t; }"
        : "=r"(a) : "l"(p));
    return a;
}
__device__ __forceinline__ void ldsm4(uint32_t* r, uint32_t a) {
    asm volatile("ldmatrix.sync.aligned.m8n8.x4.shared.b16 {%0,%1,%2,%3}, [%4];"
                 : "=r"(r[0]), "=r"(r[1]), "=r"(r[2]), "=r"(r[3]) : "r"(a));
}
__device__ __forceinline__ void mma16816(float* c, const uint32_t* a,
                                         uint32_t b0, uint32_t b1) {
    asm volatile(
        "mma.sync.aligned.m16n8k16.row.col.f32.bf16.bf16.f32 "
        "{%0,%1,%2,%3}, {%4,%5,%6,%7}, {%8,%9}, {%0,%1,%2,%3};"
        : "+f"(c[0]), "+f"(c[1]), "+f"(c[2]), "+f"(c[3])
        : "r"(a[0]), "r"(a[1]), "r"(a[2]), "r"(a[3]), "r"(b0), "r"(b1));
}
__device__ __forceinline__ float phi_f(float x) {
    return x > 0.f ? x + 1.f : __expf(x);
}
__device__ __forceinline__ uint32_t pack_bf2(float s1, float s0) {
    uint32_t r;  // low half <- s0, high half <- s1
    asm("cvt.rn.bf16x2.f32 %0, %1, %2;" : "=r"(r) : "f"(s1), "f"(s0));
    return r;
}
// u32 index in an 8KB [d(128)][sq(16)] tile, XOR-swizzled on 16B groups
__device__ __forceinline__ int stoff(int d, int sq) {
    return (d << 4) + ((((sq >> 2) ^ ((d >> 1) & 3))) << 2) + (sq & 3);
}
// byte address for a 16B row-fragment: row d, 16B-group g
__device__ __forceinline__ uint32_t frag_addr(uint32_t base, int d, int g) {
    return base + (d << 6) + (((g ^ ((d >> 1) & 3))) << 4);
}

// ---------------------------------------------------------------------------
// Phase 1. grid (NS, NBH, 2): z==0 -> Gp partial (+z), z==1 -> A partial.
// ---------------------------------------------------------------------------
__global__ __launch_bounds__(256, 2)
void drp1_kernel(const float* __restrict__ K, const float* __restrict__ V) {
    __shared__ uint32_t smA[2048];   // phi hi  [d][sq] swizzled
    __shared__ uint32_t smB[2048];   // t=0: 2*phi lo ; t=1: V hi

    const int split = blockIdx.x, bh = blockIdx.y, t = blockIdx.z;
    const int tid = threadIdx.x, w = tid >> 5, l = tid & 31;
    const int d = tid & 127, hb = tid >> 7;

    const uint32_t baseA = smem_u32(smA), baseB = smem_u32(smB);
    const float* Kb = K + ((size_t)bh * SS + (size_t)split * SR) * 128;
    const float* Vb = V + ((size_t)bh * SS + (size_t)split * SR) * 128;

    const int mb = (w & 1) * 64, nb = (w >> 1) * 32;

    float acc[4][4][4];
    #pragma unroll
    for (int mt = 0; mt < 4; mt++)
        #pragma unroll
        for (int nt = 0; nt < 4; nt++)
            #pragma unroll
            for (int q = 0; q < 4; q++) acc[mt][nt][q] = 0.f;
    float zacc = 0.f;

    for (int c = 0; c < NCH; c++) {
        const float* Kc = Kb + (size_t)c * KC * 128;
        const float* Vc = Vb + (size_t)c * KC * 128;

        // ---- stage chunk: convert + transpose into swizzled bf16 tiles ----
        #pragma unroll
        for (int i = 0; i < 8; i++) {
            const int sq = 2 * i + hb;                // 0..15
            const int off = stoff(d, sq);
            float x0 = __ldg(Kc + (size_t)(sq << 1) * 128 + d);
            float x1 = __ldg(Kc + (size_t)((sq << 1) + 1) * 128 + d);
            float p0 = phi_f(x0), p1 = phi_f(x1);
            uint32_t hi = pack_bf2(p1, p0);
            smA[off] = hi;
            if (t == 0) {
                float h0 = __uint_as_float(hi << 16);
                float h1 = __uint_as_float(hi & 0xffff0000u);
                smB[off] = pack_bf2(2.f * (p1 - h1), 2.f * (p0 - h0));
                zacc += p0 + p1;
            } else {
                float v0 = __ldg(Vc + (size_t)(sq << 1) * 128 + d);
                float v1 = __ldg(Vc + (size_t)((sq << 1) + 1) * 128 + d);
                smB[off] = pack_bf2(v1, v0);
            }
        }
        __syncthreads();

        // ---- mma ----
        #pragma unroll
        for (int ks = 0; ks < 2; ks++) {
            const int g = 2 * ks + (l >> 4);
            uint32_t af[4][4];
            #pragma unroll
            for (int mt = 0; mt < 4; mt++)
                ldsm4(af[mt], frag_addr(baseA, mb + 16 * mt + (l & 15), g));

            uint32_t bb[2][4];
            if (t == 0) {
                // pass 1: B = phi hi (smA)
                #pragma unroll
                for (int p = 0; p < 2; p++)
                    ldsm4(bb[p], frag_addr(baseA, nb + 16 * p + (l & 15), g));
                #pragma unroll
                for (int mt = 0; mt < 4; mt++)
                    #pragma unroll
                    for (int nt = 0; nt < 4; nt++)
                        mma16816(acc[mt][nt], af[mt],
                                 bb[nt >> 1][nt & 1], bb[nt >> 1][2 + (nt & 1)]);
            }
            // pass 2 (t=0: B = 2*lo) / only pass (t=1: B = V hi)
            #pragma unroll
            for (int p = 0; p < 2; p++)
                ldsm4(bb[p], frag_addr(baseB, nb + 16 * p + (l & 15), g));
            #pragma unroll
            for (int mt = 0; mt < 4; mt++)
                #pragma unroll
                for (int nt = 0; nt < 4; nt++)
                    mma16816(acc[mt][nt], af[mt],
                             bb[nt >> 1][nt & 1], bb[nt >> 1][2 + (nt & 1)]);
        }
        __syncthreads();
    }

    // ---- epilogue: write 128x128 partial ----
    float* dst = (t ? g_A : g_G) + (size_t)(bh * NS + split) * 16384;
    const int r = l >> 2, cc = 2 * (l & 3);
    #pragma unroll
    for (int mt = 0; mt < 4; mt++)
        #pragma unroll
        for (int nt = 0; nt < 4; nt++) {
            int row = mb + 16 * mt + r, col = nb + 8 * nt + cc;
            *(float2*)(dst + (size_t)row * 128 + col) =
                make_float2(acc[mt][nt][0], acc[mt][nt][1]);
            *(float2*)(dst + (size_t)(row + 8) * 128 + col) =
                make_float2(acc[mt][nt][2], acc[mt][nt][3]);
        }

    if (t == 0)
        g_z[((size_t)(bh * NS + split) * 2 + hb) * 128 + d] = zacc;
}

// ---------------------------------------------------------------------------
// Phase 2: new_M = M + A - G*M with G = (Gp + Gp^T)/2 ; new_z.
// grid (64, 2 dv-halves), 256 threads, f32x2 FMA micro-kernel.
// ---------------------------------------------------------------------------
__device__ __forceinline__ u64 pk2(float x, float y) {
    u64 r; asm("mov.b64 %0,{%1,%2};" : "=l"(r) : "f"(x), "f"(y)); return r;
}
__device__ __forceinline__ void fma2(u64& c, u64 a, u64 b) {
    asm("fma.rn.f32x2 %0,%1,%2,%0;" : "+l"(c) : "l"(a), "l"(b));
}
__device__ __forceinline__ void add2(u64& c, u64 a) {
    asm("add.rn.f32x2 %0,%1,%0;" : "+l"(c) : "l"(a));
}

#define TSL 32
#define LDG2 132

__global__ __launch_bounds__(256, 2)
void drp2_kernel(const float* __restrict__ M, const float* __restrict__ z,
                 float* __restrict__ out) {
    const int bh = blockIdx.x, half = blockIdx.y;
    __shared__ float GT[TSL * LDG2];

    const int tid = threadIdx.x;
    const int tx = tid & 15, ty = tid >> 4;
    const int ra = ty * 8, cb = half * 64 + tx * 4;

    const float* Mp = M + (size_t)bh * 16384;
    const float* A0 = g_A + (size_t)bh * NS * 16384;
    const float* G0 = g_G + (size_t)bh * NS * 16384;

    u64 acc[8][2];
    #pragma unroll
    for (int i = 0; i < 8; i++) {
        #pragma unroll
        for (int p = 0; p < 2; p++) {
            size_t o = (size_t)(ra + i) * 128 + cb + 2 * p;
            float2 m = *(const float2*)(Mp + o);
            u64 a = pk2(m.x, m.y);
            #pragma unroll
            for (int c = 0; c < NS; c++)
                add2(a, *(const u64*)(A0 + (size_t)c * 16384 + o));
            acc[i][p] = a;
        }
    }

    for (int ks = 0; ks < 128; ks += TSL) {
        __syncthreads();
        for (int e = tid; e < 128 * TSL; e += 256) {
            int i = e >> 5, kk = e & 31, k = ks + kk;
            float s = 0.f;
            #pragma unroll
            for (int c = 0; c < NS; c++)
                s += G0[(size_t)c * 16384 + (size_t)i * 128 + k] +
                     G0[(size_t)c * 16384 + (size_t)k * 128 + i];
            GT[kk * LDG2 + i] = 0.5f * s;
        }
        __syncthreads();

        #pragma unroll 4
        for (int kk = 0; kk < TSL; kk++) {
            int k = ks + kk;
            float4 a0 = *(const float4*)(GT + kk * LDG2 + ra);
            float4 a1 = *(const float4*)(GT + kk * LDG2 + ra + 4);
            float4 b = __ldg((const float4*)(Mp + (size_t)k * 128 + cb));
            u64 bp0 = pk2(b.x, b.y), bp1 = pk2(b.z, b.w);
            float av[8] = {a0.x, a0.y, a0.z, a0.w, a1.x, a1.y, a1.z, a1.w};
            #pragma unroll
            for (int i = 0; i < 8; i++) {
                u64 pa = pk2(-av[i], -av[i]);
                fma2(acc[i][0], pa, bp0);
                fma2(acc[i][1], pa, bp1);
            }
        }
    }

    float* outM = out + (size_t)bh * 16384;
    #pragma unroll
    for (int i = 0; i < 8; i++)
        #pragma unroll
        for (int p = 0; p < 2; p++)
            *(u64*)(outM + (size_t)(ra + i) * 128 + cb + 2 * p) = acc[i][p];

    if (half == 0 && tid < 128) {
        float s = z[(size_t)bh * 128 + tid];
        #pragma unroll
        for (int j = 0; j < 2 * NS; j++)
            s += g_z[(size_t)bh * (2 * NS * 128) + (size_t)j * 128 + tid];
        out[(size_t)NBH * 16384 + (size_t)bh * 128 + tid] = s;
    }
}

extern "C" void kernel_launch(void* const* d_in, const int* in_sizes, int n_in,
                              void* d_out, int out_size) {
    const float* K = (const float*)d_in[0];
    const float* V = (const float*)d_in[1];
    const float* M = (const float*)d_in[2];
    const float* z = (const float*)d_in[3];
    float* out = (float*)d_out;

    drp1_kernel<<<dim3(NS, NBH, 2), 256>>>(K, V);
    drp2_kernel<<<dim3(NBH, 2), 256>>>(M, z, out);
}

// round 6
// speedup vs baseline: 4.2089x; 2.3712x over previous
#include <cuda_runtime.h>
#include <cuda_fp16.h>
#include <cstdint>

// new_M = M + phi^T V - (phi^T phi) M ; new_z = z + colsum(phi); phi = elu(K)+1
// K,V: (64, 8192, 128) fp32 flattened over (b,h).
// Phase1: fused fp16 mma.sync: per CTA stage phi+V once; 8 warps compute
//   G = phi^T phi (exactly symmetric), 8 warps compute A = phi^T V.
// Phase2: reduce partials, new_M = M + A - G*M (no transpose needed), new_z.

#define SS 8192
#define NBH 64
#define NS 4                 // S-splits per bh
#define SR (SS / NS)         // 2048
#define KC 32                // s per staged chunk
#define NCH (SR / KC)        // 64

__device__ float g_G[(size_t)NBH * NS * 16384];
__device__ float g_A[(size_t)NBH * NS * 16384];
__device__ float g_z[(size_t)NBH * NS * 8 * 128];

typedef unsigned long long u64;

// ---------------- helpers ----------------
__device__ __forceinline__ uint32_t smem_u32(const void* p) {
    uint32_t a;
    asm("{ .reg .u64 t; cvta.to.shared.u64 t, %1; cvt.u32.u64 %0, t; }"
        : "=r"(a) : "l"(p));
    return a;
}
__device__ __forceinline__ void ldsm4(uint32_t* r, uint32_t a) {
    asm volatile("ldmatrix.sync.aligned.m8n8.x4.shared.b16 {%0,%1,%2,%3}, [%4];"
                 : "=r"(r[0]), "=r"(r[1]), "=r"(r[2]), "=r"(r[3]) : "r"(a));
}
__device__ __forceinline__ void mma16816(float* c, const uint32_t* a,
                                         uint32_t b0, uint32_t b1) {
    asm volatile(
        "mma.sync.aligned.m16n8k16.row.col.f32.f16.f16.f32 "
        "{%0,%1,%2,%3}, {%4,%5,%6,%7}, {%8,%9}, {%0,%1,%2,%3};"
        : "+f"(c[0]), "+f"(c[1]), "+f"(c[2]), "+f"(c[3])
        : "r"(a[0]), "r"(a[1]), "r"(a[2]), "r"(a[3]), "r"(b0), "r"(b1));
}
__device__ __forceinline__ float phi_f(float x) {
    return x > 0.f ? x + 1.f : __expf(x);
}
__device__ __forceinline__ uint32_t packh2(float s1, float s0) {
    uint32_t r;  // low half <- s0, high half <- s1
    asm("cvt.rn.f16x2.f32 %0, %1, %2;" : "=r"(r) : "f"(s1), "f"(s0));
    return r;
}
// u32 index in an 8KB [d(128)][sq(16)] tile, XOR-swizzled on 16B groups
__device__ __forceinline__ int stoff(int d, int sq) {
    return (d << 4) + ((((sq >> 2) ^ ((d >> 1) & 3))) << 2) + (sq & 3);
}
// byte address for a 16B row-fragment: row d, 16B-group g
__device__ __forceinline__ uint32_t frag_addr(uint32_t base, int d, int g) {
    return base + (d << 6) + (((g ^ ((d >> 1) & 3))) << 4);
}

// ---------------------------------------------------------------------------
// Phase 1. grid (NS, NBH), 512 threads. Warps 0-7: G, warps 8-15: A.
// ---------------------------------------------------------------------------
__global__ __launch_bounds__(512, 1)
void drp1_kernel(const float* __restrict__ K, const float* __restrict__ V) {
    __shared__ uint32_t smA[2048];   // phi fp16x2 [d][sq] swizzled
    __shared__ uint32_t smB[2048];   // V   fp16x2 [d][sq] swizzled

    const int split = blockIdx.x, bh = blockIdx.y;
    const int tid = threadIdx.x, w = tid >> 5, l = tid & 31;
    const int tg = w >> 3, w8 = w & 7;
    const int mb = (w8 & 1) * 64, nb = (w8 >> 1) * 32;
    const int d2 = tid & 63;          // d-pair owner
    const int sq0 = tid >> 6;         // 0..7

    const uint32_t baseA = smem_u32(smA), baseB = smem_u32(smB);
    const uint32_t baseOp = tg ? baseB : baseA;
    const float* Kb = K + ((size_t)bh * SS + (size_t)split * SR) * 128;
    const float* Vb = V + ((size_t)bh * SS + (size_t)split * SR) * 128;

    float acc[4][4][4];
    #pragma unroll
    for (int mt = 0; mt < 4; mt++)
        #pragma unroll
        for (int nt = 0; nt < 4; nt++)
            #pragma unroll
            for (int q = 0; q < 4; q++) acc[mt][nt][q] = 0.f;
    float z0 = 0.f, z1 = 0.f;

    // prefetch chunk 0
    float2 kp[4], vp[4];
    {
        const float* Kc = Kb;
        const float* Vc = Vb;
        #pragma unroll
        for (int j = 0; j < 2; j++) {
            const float* kr = Kc + (size_t)((sq0 + 8 * j) << 1) * 128 + 2 * d2;
            const float* vr = Vc + (size_t)((sq0 + 8 * j) << 1) * 128 + 2 * d2;
            kp[2 * j] = __ldg((const float2*)kr);
            kp[2 * j + 1] = __ldg((const float2*)(kr + 128));
            vp[2 * j] = __ldg((const float2*)vr);
            vp[2 * j + 1] = __ldg((const float2*)(vr + 128));
        }
    }

    for (int c = 0; c < NCH; c++) {
        // ---- convert + store staged tiles ----
        #pragma unroll
        for (int j = 0; j < 2; j++) {
            const int sq = sq0 + 8 * j;
            float p00 = phi_f(kp[2 * j].x),     p01 = phi_f(kp[2 * j].y);
            float p10 = phi_f(kp[2 * j + 1].x), p11 = phi_f(kp[2 * j + 1].y);
            smA[stoff(2 * d2, sq)]     = packh2(p10, p00);
            smA[stoff(2 * d2 + 1, sq)] = packh2(p11, p01);
            z0 += p00 + p10;
            z1 += p01 + p11;
            smB[stoff(2 * d2, sq)]     = packh2(vp[2 * j + 1].x, vp[2 * j].x);
            smB[stoff(2 * d2 + 1, sq)] = packh2(vp[2 * j + 1].y, vp[2 * j].y);
        }
        __syncthreads();

        // ---- prefetch chunk c+1 (hidden under MMA below) ----
        if (c + 1 < NCH) {
            const float* Kc = Kb + (size_t)(c + 1) * KC * 128;
            const float* Vc = Vb + (size_t)(c + 1) * KC * 128;
            #pragma unroll
            for (int j = 0; j < 2; j++) {
                const float* kr = Kc + (size_t)((sq0 + 8 * j) << 1) * 128 + 2 * d2;
                const float* vr = Vc + (size_t)((sq0 + 8 * j) << 1) * 128 + 2 * d2;
                kp[2 * j] = __ldg((const float2*)kr);
                kp[2 * j + 1] = __ldg((const float2*)(kr + 128));
                vp[2 * j] = __ldg((const float2*)vr);
                vp[2 * j + 1] = __ldg((const float2*)(vr + 128));
            }
        }

        // ---- mma ----
        #pragma unroll
        for (int ks = 0; ks < 2; ks++) {
            const int g = 2 * ks + (l >> 4);
            uint32_t af[4][4];
            #pragma unroll
            for (int mt = 0; mt < 4; mt++)
                ldsm4(af[mt], frag_addr(baseA, mb + 16 * mt + (l & 15), g));
            uint32_t bb[2][4];
            #pragma unroll
            for (int p = 0; p < 2; p++)
                ldsm4(bb[p], frag_addr(baseOp, nb + 16 * p + (l & 15), g));
            #pragma unroll
            for (int mt = 0; mt < 4; mt++)
                #pragma unroll
                for (int nt = 0; nt < 4; nt++)
                    mma16816(acc[mt][nt], af[mt],
                             bb[nt >> 1][nt & 1], bb[nt >> 1][2 + (nt & 1)]);
        }
        __syncthreads();
    }

    // ---- epilogue: write 128x128 partial ----
    float* dst = (tg ? g_A : g_G) + (size_t)(bh * NS + split) * 16384;
    const int r = l >> 2, cc = 2 * (l & 3);
    #pragma unroll
    for (int mt = 0; mt < 4; mt++)
        #pragma unroll
        for (int nt = 0; nt < 4; nt++) {
            int row = mb + 16 * mt + r, col = nb + 8 * nt + cc;
            *(float2*)(dst + (size_t)row * 128 + col) =
                make_float2(acc[mt][nt][0], acc[mt][nt][1]);
            *(float2*)(dst + (size_t)(row + 8) * 128 + col) =
                make_float2(acc[mt][nt][2], acc[mt][nt][3]);
        }

    // z partials (each thread owns a unique (group, d-pair) slot)
    *(float2*)(g_z + ((size_t)(bh * NS + split) * 8 + sq0) * 128 + 2 * d2) =
        make_float2(z0, z1);
}

// ---------------------------------------------------------------------------
// Phase 2: new_M = M + A - G*M (G symmetric by construction); new_z.
// grid (64 bh, 4 dv-quarters), 256 threads, f32x2 FMA micro-kernel.
// ---------------------------------------------------------------------------
__device__ __forceinline__ u64 pk2(float x, float y) {
    u64 r; asm("mov.b64 %0,{%1,%2};" : "=l"(r) : "f"(x), "f"(y)); return r;
}
__device__ __forceinline__ void fma2(u64& c, u64 a, u64 b) {
    asm("fma.rn.f32x2 %0,%1,%2,%0;" : "+l"(c) : "l"(a), "l"(b));
}
__device__ __forceinline__ void add2(u64& c, u64 a) {
    asm("add.rn.f32x2 %0,%1,%0;" : "+l"(c) : "l"(a));
}

__global__ __launch_bounds__(256, 4)
void drp2_kernel(const float* __restrict__ M, const float* __restrict__ z,
                 float* __restrict__ out) {
    const int bh = blockIdx.x, q = blockIdx.y;
    __shared__ float GT[128 * 33];    // GT[i][kk], pad 33: conflict-free r/w

    const int tid = threadIdx.x;
    const int tx = tid & 7, ty = tid >> 3;   // 8 col-groups x 32 row-groups
    const int ra = ty * 4;                    // 4 rows
    const int cb = q * 32 + tx * 4;           // 4 cols

    const float* Mp = M + (size_t)bh * 16384;
    const float* A0 = g_A + (size_t)bh * NS * 16384;
    const float* G0 = g_G + (size_t)bh * NS * 16384;

    u64 acc[4][2];
    #pragma unroll
    for (int i = 0; i < 4; i++) {
        #pragma unroll
        for (int p = 0; p < 2; p++) {
            size_t o = (size_t)(ra + i) * 128 + cb + 2 * p;
            float2 m = *(const float2*)(Mp + o);
            u64 a = pk2(m.x, m.y);
            #pragma unroll
            for (int c = 0; c < NS; c++)
                add2(a, *(const u64*)(A0 + (size_t)c * 16384 + o));
            acc[i][p] = a;
        }
    }

    for (int ks = 0; ks < 128; ks += 32) {
        __syncthreads();
        for (int e = tid; e < 128 * 32; e += 256) {
            int kk = e & 31, i = e >> 5;
            float s = 0.f;
            #pragma unroll
            for (int c = 0; c < NS; c++)
                s += G0[(size_t)c * 16384 + (size_t)i * 128 + ks + kk];
            GT[i * 33 + kk] = s;
        }
        __syncthreads();

        #pragma unroll 4
        for (int kk = 0; kk < 32; kk++) {
            int k = ks + kk;
            float gv[4];
            #pragma unroll
            for (int i = 0; i < 4; i++) gv[i] = GT[(ra + i) * 33 + kk];
            float4 b = __ldg((const float4*)(Mp + (size_t)k * 128 + cb));
            u64 b0 = pk2(b.x, b.y), b1 = pk2(b.z, b.w);
            #pragma unroll
            for (int i = 0; i < 4; i++) {
                u64 pa = pk2(-gv[i], -gv[i]);
                fma2(acc[i][0], pa, b0);
                fma2(acc[i][1], pa, b1);
            }
        }
    }

    float* outM = out + (size_t)bh * 16384;
    #pragma unroll
    for (int i = 0; i < 4; i++)
        #pragma unroll
        for (int p = 0; p < 2; p++)
            *(u64*)(outM + (size_t)(ra + i) * 128 + cb + 2 * p) = acc[i][p];

    if (q == 0 && tid < 128) {
        float s = z[(size_t)bh * 128 + tid];
        #pragma unroll
        for (int j = 0; j < NS * 8; j++)
            s += g_z[((size_t)bh * NS * 8 + j) * 128 + tid];
        out[(size_t)NBH * 16384 + (size_t)bh * 128 + tid] = s;
    }
}

extern "C" void kernel_launch(void* const* d_in, const int* in_sizes, int n_in,
                              void* d_out, int out_size) {
    const float* K = (const float*)d_in[0];
    const float* V = (const float*)d_in[1];
    const float* M = (const float*)d_in[2];
    const float* z = (const float*)d_in[3];
    float* out = (float*)d_out;

    drp1_kernel<<<dim3(NS, NBH), 512>>>(K, V);
    drp2_kernel<<<dim3(NBH, 4), 256>>>(M, z, out);
}

// round 7
// speedup vs baseline: 4.5190x; 1.0737x over previous
#include <cuda_runtime.h>
#include <cuda_fp16.h>
#include <cstdint>

// new_M = M + phi^T V - (phi^T phi) M ; new_z = z + colsum(phi); phi = elu(K)+1
// K,V: (64, 8192, 128) fp32 flattened over (b,h).
// Phase1: fused fp16 mma.sync, double-buffered smem, 1 barrier/chunk.
//   Warps 0-7: G = phi^T phi (symmetric), warps 8-15: A = phi^T V.
// Phase2: reduce partials, new_M = M + A - G*M, new_z. 512 threads/CTA.

#define SS 8192
#define NBH 64
#define NS 4                 // S-splits per bh
#define SR (SS / NS)         // 2048
#define KC 32                // s per staged chunk
#define NCH (SR / KC)        // 64

__device__ float g_G[(size_t)NBH * NS * 16384];
__device__ float g_A[(size_t)NBH * NS * 16384];
__device__ float g_z[(size_t)NBH * NS * 8 * 128];

typedef unsigned long long u64;

// ---------------- helpers ----------------
__device__ __forceinline__ uint32_t smem_u32(const void* p) {
    uint32_t a;
    asm("{ .reg .u64 t; cvta.to.shared.u64 t, %1; cvt.u32.u64 %0, t; }"
        : "=r"(a) : "l"(p));
    return a;
}
__device__ __forceinline__ void ldsm4(uint32_t* r, uint32_t a) {
    asm volatile("ldmatrix.sync.aligned.m8n8.x4.shared.b16 {%0,%1,%2,%3}, [%4];"
                 : "=r"(r[0]), "=r"(r[1]), "=r"(r[2]), "=r"(r[3]) : "r"(a));
}
__device__ __forceinline__ void mma16816(float* c, const uint32_t* a,
                                         uint32_t b0, uint32_t b1) {
    asm volatile(
        "mma.sync.aligned.m16n8k16.row.col.f32.f16.f16.f32 "
        "{%0,%1,%2,%3}, {%4,%5,%6,%7}, {%8,%9}, {%0,%1,%2,%3};"
        : "+f"(c[0]), "+f"(c[1]), "+f"(c[2]), "+f"(c[3])
        : "r"(a[0]), "r"(a[1]), "r"(a[2]), "r"(a[3]), "r"(b0), "r"(b1));
}
__device__ __forceinline__ float phi_f(float x) {
    return x > 0.f ? x + 1.f : __expf(x);
}
__device__ __forceinline__ uint32_t packh2(float s1, float s0) {
    uint32_t r;  // low half <- s0, high half <- s1
    asm("cvt.rn.f16x2.f32 %0, %1, %2;" : "=r"(r) : "f"(s1), "f"(s0));
    return r;
}
// u32 index in an 8KB [d(128)][sq(16)] tile, XOR-swizzled on 16B groups
__device__ __forceinline__ int stoff(int d, int sq) {
    return (d << 4) + ((((sq >> 2) ^ ((d >> 1) & 3))) << 2) + (sq & 3);
}
// byte address for a 16B row-fragment: row d, 16B-group g
__device__ __forceinline__ uint32_t frag_addr(uint32_t base, int d, int g) {
    return base + (d << 6) + (((g ^ ((d >> 1) & 3))) << 4);
}

// ---------------------------------------------------------------------------
// Phase 1. grid (NS, NBH), 512 threads. Warps 0-7: G, warps 8-15: A.
// Double-buffered tiles, one __syncthreads per chunk.
// ---------------------------------------------------------------------------
__global__ __launch_bounds__(512, 1)
void drp1_kernel(const float* __restrict__ K, const float* __restrict__ V) {
    __shared__ uint32_t smA[2][2048];   // phi fp16x2 [d][sq] swizzled
    __shared__ uint32_t smB[2][2048];   // V   fp16x2 [d][sq] swizzled

    const int split = blockIdx.x, bh = blockIdx.y;
    const int tid = threadIdx.x, w = tid >> 5, l = tid & 31;
    const int tg = w >> 3, w8 = w & 7;
    const int mb = (w8 & 1) * 64, nb = (w8 >> 1) * 32;
    const int d2 = tid & 63;          // d-pair owner
    const int sq0 = tid >> 6;         // 0..7

    const uint32_t baseA0 = smem_u32(smA), baseB0 = smem_u32(smB);
    const float* Kb = K + ((size_t)bh * SS + (size_t)split * SR) * 128;
    const float* Vb = V + ((size_t)bh * SS + (size_t)split * SR) * 128;

    float acc[4][4][4];
    #pragma unroll
    for (int mt = 0; mt < 4; mt++)
        #pragma unroll
        for (int nt = 0; nt < 4; nt++)
            #pragma unroll
            for (int qq = 0; qq < 4; qq++) acc[mt][nt][qq] = 0.f;
    float z0 = 0.f, z1 = 0.f;

    float2 kp[4], vp[4];

    // ---- load chunk 0 ----
    #pragma unroll
    for (int j = 0; j < 2; j++) {
        const float* kr = Kb + (size_t)((sq0 + 8 * j) << 1) * 128 + 2 * d2;
        const float* vr = Vb + (size_t)((sq0 + 8 * j) << 1) * 128 + 2 * d2;
        kp[2 * j] = __ldg((const float2*)kr);
        kp[2 * j + 1] = __ldg((const float2*)(kr + 128));
        vp[2 * j] = __ldg((const float2*)vr);
        vp[2 * j + 1] = __ldg((const float2*)(vr + 128));
    }
    // ---- convert + store chunk 0 into buf 0 ----
    #pragma unroll
    for (int j = 0; j < 2; j++) {
        const int sq = sq0 + 8 * j;
        float p00 = phi_f(kp[2 * j].x),     p01 = phi_f(kp[2 * j].y);
        float p10 = phi_f(kp[2 * j + 1].x), p11 = phi_f(kp[2 * j + 1].y);
        smA[0][stoff(2 * d2, sq)]     = packh2(p10, p00);
        smA[0][stoff(2 * d2 + 1, sq)] = packh2(p11, p01);
        z0 += p00 + p10;
        z1 += p01 + p11;
        smB[0][stoff(2 * d2, sq)]     = packh2(vp[2 * j + 1].x, vp[2 * j].x);
        smB[0][stoff(2 * d2 + 1, sq)] = packh2(vp[2 * j + 1].y, vp[2 * j].y);
    }
    __syncthreads();

    for (int c = 0; c < NCH; c++) {
        const int buf = c & 1, nbuf = buf ^ 1;
        const bool has_next = (c + 1 < NCH);

        // ---- prefetch chunk c+1 (lands during MMA below) ----
        if (has_next) {
            const float* Kc = Kb + (size_t)(c + 1) * KC * 128;
            const float* Vc = Vb + (size_t)(c + 1) * KC * 128;
            #pragma unroll
            for (int j = 0; j < 2; j++) {
                const float* kr = Kc + (size_t)((sq0 + 8 * j) << 1) * 128 + 2 * d2;
                const float* vr = Vc + (size_t)((sq0 + 8 * j) << 1) * 128 + 2 * d2;
                kp[2 * j] = __ldg((const float2*)kr);
                kp[2 * j + 1] = __ldg((const float2*)(kr + 128));
                vp[2 * j] = __ldg((const float2*)vr);
                vp[2 * j + 1] = __ldg((const float2*)(vr + 128));
            }
        }

        // ---- mma on buf ----
        {
            const uint32_t bA = baseA0 + (uint32_t)buf * 8192;
            const uint32_t bOp = (tg ? baseB0 : baseA0) + (uint32_t)buf * 8192;
            #pragma unroll
            for (int ks = 0; ks < 2; ks++) {
                const int g = 2 * ks + (l >> 4);
                uint32_t af[4][4];
                #pragma unroll
                for (int mt = 0; mt < 4; mt++)
                    ldsm4(af[mt], frag_addr(bA, mb + 16 * mt + (l & 15), g));
                uint32_t bb[2][4];
                #pragma unroll
                for (int p = 0; p < 2; p++)
                    ldsm4(bb[p], frag_addr(bOp, nb + 16 * p + (l & 15), g));
                #pragma unroll
                for (int mt = 0; mt < 4; mt++)
                    #pragma unroll
                    for (int nt = 0; nt < 4; nt++)
                        mma16816(acc[mt][nt], af[mt],
                                 bb[nt >> 1][nt & 1], bb[nt >> 1][2 + (nt & 1)]);
            }
        }

        // ---- convert + store chunk c+1 into nbuf ----
        if (has_next) {
            #pragma unroll
            for (int j = 0; j < 2; j++) {
                const int sq = sq0 + 8 * j;
                float p00 = phi_f(kp[2 * j].x),     p01 = phi_f(kp[2 * j].y);
                float p10 = phi_f(kp[2 * j + 1].x), p11 = phi_f(kp[2 * j + 1].y);
                smA[nbuf][stoff(2 * d2, sq)]     = packh2(p10, p00);
                smA[nbuf][stoff(2 * d2 + 1, sq)] = packh2(p11, p01);
                z0 += p00 + p10;
                z1 += p01 + p11;
                smB[nbuf][stoff(2 * d2, sq)]     = packh2(vp[2 * j + 1].x, vp[2 * j].x);
                smB[nbuf][stoff(2 * d2 + 1, sq)] = packh2(vp[2 * j + 1].y, vp[2 * j].y);
            }
        }
        __syncthreads();
    }

    // ---- epilogue: write 128x128 partial ----
    float* dst = (tg ? g_A : g_G) + (size_t)(bh * NS + split) * 16384;
    const int r = l >> 2, cc = 2 * (l & 3);
    #pragma unroll
    for (int mt = 0; mt < 4; mt++)
        #pragma unroll
        for (int nt = 0; nt < 4; nt++) {
            int row = mb + 16 * mt + r, col = nb + 8 * nt + cc;
            *(float2*)(dst + (size_t)row * 128 + col) =
                make_float2(acc[mt][nt][0], acc[mt][nt][1]);
            *(float2*)(dst + (size_t)(row + 8) * 128 + col) =
                make_float2(acc[mt][nt][2], acc[mt][nt][3]);
        }

    // z partials (each thread owns a unique (group, d-pair) slot)
    *(float2*)(g_z + ((size_t)(bh * NS + split) * 8 + sq0) * 128 + 2 * d2) =
        make_float2(z0, z1);
}

// ---------------------------------------------------------------------------
// Phase 2: new_M = M + A - G*M (G symmetric by construction); new_z.
// grid (64 bh, 4 dv-quarters), 512 threads, 2x4 micro-tile, f32x2 FMA.
// ---------------------------------------------------------------------------
__device__ __forceinline__ u64 pk2(float x, float y) {
    u64 r; asm("mov.b64 %0,{%1,%2};" : "=l"(r) : "f"(x), "f"(y)); return r;
}
__device__ __forceinline__ void fma2(u64& c, u64 a, u64 b) {
    asm("fma.rn.f32x2 %0,%1,%2,%0;" : "+l"(c) : "l"(a), "l"(b));
}
__device__ __forceinline__ void add2(u64& c, u64 a) {
    asm("add.rn.f32x2 %0,%1,%0;" : "+l"(c) : "l"(a));
}

__global__ __launch_bounds__(512, 2)
void drp2_kernel(const float* __restrict__ M, const float* __restrict__ z,
                 float* __restrict__ out) {
    const int bh = blockIdx.x, q = blockIdx.y;
    __shared__ float GT[128 * 33];    // GT[i][kk], pad 33

    const int tid = threadIdx.x;
    const int tx = tid & 7, ty = tid >> 3;    // 8 col-groups x 64 row-groups
    const int ra = ty * 2;                    // 2 rows
    const int cb = q * 32 + tx * 4;           // 4 cols

    const float* Mp = M + (size_t)bh * 16384;
    const float* A0 = g_A + (size_t)bh * NS * 16384;
    const float* G0 = g_G + (size_t)bh * NS * 16384;

    u64 acc[2][2];
    #pragma unroll
    for (int i = 0; i < 2; i++) {
        #pragma unroll
        for (int p = 0; p < 2; p++) {
            size_t o = (size_t)(ra + i) * 128 + cb + 2 * p;
            float2 m = *(const float2*)(Mp + o);
            u64 a = pk2(m.x, m.y);
            #pragma unroll
            for (int c = 0; c < NS; c++)
                add2(a, *(const u64*)(A0 + (size_t)c * 16384 + o));
            acc[i][p] = a;
        }
    }

    for (int ks = 0; ks < 128; ks += 32) {
        __syncthreads();
        for (int e = tid; e < 128 * 32; e += 512) {
            int kk = e & 31, i = e >> 5;
            float s = 0.f;
            #pragma unroll
            for (int c = 0; c < NS; c++)
                s += G0[(size_t)c * 16384 + (size_t)i * 128 + ks + kk];
            GT[i * 33 + kk] = s;
        }
        __syncthreads();

        #pragma unroll 8
        for (int kk = 0; kk < 32; kk++) {
            int k = ks + kk;
            float g0 = GT[(ra + 0) * 33 + kk];
            float g1 = GT[(ra + 1) * 33 + kk];
            float4 b = __ldg((const float4*)(Mp + (size_t)k * 128 + cb));
            u64 b0 = pk2(b.x, b.y), b1 = pk2(b.z, b.w);
            u64 pa0 = pk2(-g0, -g0), pa1 = pk2(-g1, -g1);
            fma2(acc[0][0], pa0, b0);
            fma2(acc[0][1], pa0, b1);
            fma2(acc[1][0], pa1, b0);
            fma2(acc[1][1], pa1, b1);
        }
    }

    float* outM = out + (size_t)bh * 16384;
    #pragma unroll
    for (int i = 0; i < 2; i++)
        #pragma unroll
        for (int p = 0; p < 2; p++)
            *(u64*)(outM + (size_t)(ra + i) * 128 + cb + 2 * p) = acc[i][p];

    if (q == 0 && tid < 128) {
        float s = z[(size_t)bh * 128 + tid];
        #pragma unroll
        for (int j = 0; j < NS * 8; j++)
            s += g_z[((size_t)bh * NS * 8 + j) * 128 + tid];
        out[(size_t)NBH * 16384 + (size_t)bh * 128 + tid] = s;
    }
}

extern "C" void kernel_launch(void* const* d_in, const int* in_sizes, int n_in,
                              void* d_out, int out_size) {
    const float* K = (const float*)d_in[0];
    const float* V = (const float*)d_in[1];
    const float* M = (const float*)d_in[2];
    const float* z = (const float*)d_in[3];
    float* out = (float*)d_out;

    drp1_kernel<<<dim3(NS, NBH), 512>>>(K, V);
    drp2_kernel<<<dim3(NBH, 4), 512>>>(M, z, out);
}

// round 8
// speedup vs baseline: 4.8877x; 1.0816x over previous
#include <cuda_runtime.h>
#include <cuda_fp16.h>
#include <cstdint>

// new_M = M + phi^T V - (phi^T phi) M ; new_z = z + colsum(phi); phi = elu(K)+1
// K,V: (64, 8192, 128) fp32 flattened over (b,h).
// Phase1: fused fp16 mma.sync. Warps 0-7: G = phi^T phi via symmetric band
//   tiling (band b computes cols [16b,128), mirror by transposed stores).
//   Warps 8-15: A = phi^T V with 64x32 tiles.
// Phase2: reduce partials, new_M = M + A - G*M, new_z. M staged in smem.

#define SS 8192
#define NBH 64
#define NS 2                 // S-splits per bh
#define SR (SS / NS)         // 4096
#define KC 32                // s per staged chunk
#define NCH (SR / KC)        // 128

__device__ float g_G[(size_t)NBH * NS * 16384];
__device__ float g_A[(size_t)NBH * NS * 16384];
__device__ float g_z[(size_t)NBH * NS * 8 * 128];

typedef unsigned long long u64;

// ---------------- helpers ----------------
__device__ __forceinline__ uint32_t smem_u32(const void* p) {
    uint32_t a;
    asm("{ .reg .u64 t; cvta.to.shared.u64 t, %1; cvt.u32.u64 %0, t; }"
        : "=r"(a) : "l"(p));
    return a;
}
__device__ __forceinline__ void ldsm4(uint32_t* r, uint32_t a) {
    asm volatile("ldmatrix.sync.aligned.m8n8.x4.shared.b16 {%0,%1,%2,%3}, [%4];"
                 : "=r"(r[0]), "=r"(r[1]), "=r"(r[2]), "=r"(r[3]) : "r"(a));
}
__device__ __forceinline__ void mma16816(float* c, const uint32_t* a,
                                         uint32_t b0, uint32_t b1) {
    asm volatile(
        "mma.sync.aligned.m16n8k16.row.col.f32.f16.f16.f32 "
        "{%0,%1,%2,%3}, {%4,%5,%6,%7}, {%8,%9}, {%0,%1,%2,%3};"
        : "+f"(c[0]), "+f"(c[1]), "+f"(c[2]), "+f"(c[3])
        : "r"(a[0]), "r"(a[1]), "r"(a[2]), "r"(a[3]), "r"(b0), "r"(b1));
}
__device__ __forceinline__ float phi_f(float x) {
    return x > 0.f ? x + 1.f : __expf(x);
}
__device__ __forceinline__ uint32_t packh2(float s1, float s0) {
    uint32_t r;  // low half <- s0, high half <- s1
    asm("cvt.rn.f16x2.f32 %0, %1, %2;" : "=r"(r) : "f"(s1), "f"(s0));
    return r;
}
// u32 index in an 8KB [d(128)][sq(16)] tile, XOR-swizzled on 16B groups
__device__ __forceinline__ int stoff(int d, int sq) {
    return (d << 4) + ((((sq >> 2) ^ ((d >> 1) & 3))) << 2) + (sq & 3);
}
// byte address for a 16B row-fragment: row d, 16B-group g
__device__ __forceinline__ uint32_t frag_addr(uint32_t base, int d, int g) {
    return base + (d << 6) + (((g ^ ((d >> 1) & 3))) << 4);
}

// ---------------------------------------------------------------------------
// Phase 1. grid (NS, NBH), 512 threads.
// ---------------------------------------------------------------------------
__global__ __launch_bounds__(512, 1)
void drp1_kernel(const float* __restrict__ K, const float* __restrict__ V) {
    __shared__ uint32_t smA[2][2048];   // phi fp16x2 [d][sq] swizzled
    __shared__ uint32_t smB[2][2048];   // V   fp16x2 [d][sq] swizzled

    const int split = blockIdx.x, bh = blockIdx.y;
    const int tid = threadIdx.x, w = tid >> 5, l = tid & 31;
    const int tg = w >> 3, w8 = w & 7;
    // A warps (tg=1): 64x32 tile
    const int mb = (w8 & 1) * 64, nb = (w8 >> 1) * 32;
    // G warps (tg=0): band b, SMSP-balanced pairing (b, 7-b)
    const int band = (w8 < 4) ? w8 : 11 - w8;
    const int rbase = band * 16;
    const int ntlo = 2 * band;
    const int d2 = tid & 63;          // d-pair owner (staging)
    const int sq0 = tid >> 6;         // 0..7

    const uint32_t baseA0 = smem_u32(smA), baseB0 = smem_u32(smB);
    const float* Kb = K + ((size_t)bh * SS + (size_t)split * SR) * 128;
    const float* Vb = V + ((size_t)bh * SS + (size_t)split * SR) * 128;

    float acc[16][4];                 // G: [nt][q] (nt>=ntlo); A: [mt*4+nt][q]
    #pragma unroll
    for (int i = 0; i < 16; i++)
        #pragma unroll
        for (int qq = 0; qq < 4; qq++) acc[i][qq] = 0.f;
    float z0 = 0.f, z1 = 0.f;

    float2 kp[4], vp[4];

    // ---- load chunk 0 ----
    #pragma unroll
    for (int j = 0; j < 2; j++) {
        const float* kr = Kb + (size_t)((sq0 + 8 * j) << 1) * 128 + 2 * d2;
        const float* vr = Vb + (size_t)((sq0 + 8 * j) << 1) * 128 + 2 * d2;
        kp[2 * j] = __ldg((const float2*)kr);
        kp[2 * j + 1] = __ldg((const float2*)(kr + 128));
        vp[2 * j] = __ldg((const float2*)vr);
        vp[2 * j + 1] = __ldg((const float2*)(vr + 128));
    }
    // ---- convert + store chunk 0 into buf 0 ----
    #pragma unroll
    for (int j = 0; j < 2; j++) {
        const int sq = sq0 + 8 * j;
        float p00 = phi_f(kp[2 * j].x),     p01 = phi_f(kp[2 * j].y);
        float p10 = phi_f(kp[2 * j + 1].x), p11 = phi_f(kp[2 * j + 1].y);
        smA[0][stoff(2 * d2, sq)]     = packh2(p10, p00);
        smA[0][stoff(2 * d2 + 1, sq)] = packh2(p11, p01);
        z0 += p00 + p10;
        z1 += p01 + p11;
        smB[0][stoff(2 * d2, sq)]     = packh2(vp[2 * j + 1].x, vp[2 * j].x);
        smB[0][stoff(2 * d2 + 1, sq)] = packh2(vp[2 * j + 1].y, vp[2 * j].y);
    }
    __syncthreads();

    for (int c = 0; c < NCH; c++) {
        const int buf = c & 1, nbuf = buf ^ 1;
        const bool has_next = (c + 1 < NCH);

        // ---- prefetch chunk c+1 ----
        if (has_next) {
            const float* Kc = Kb + (size_t)(c + 1) * KC * 128;
            const float* Vc = Vb + (size_t)(c + 1) * KC * 128;
            #pragma unroll
            for (int j = 0; j < 2; j++) {
                const float* kr = Kc + (size_t)((sq0 + 8 * j) << 1) * 128 + 2 * d2;
                const float* vr = Vc + (size_t)((sq0 + 8 * j) << 1) * 128 + 2 * d2;
                kp[2 * j] = __ldg((const float2*)kr);
                kp[2 * j + 1] = __ldg((const float2*)(kr + 128));
                vp[2 * j] = __ldg((const float2*)vr);
                vp[2 * j + 1] = __ldg((const float2*)(vr + 128));
            }
        }

        // ---- mma on buf ----
        {
            const uint32_t bA = baseA0 + (uint32_t)buf * 8192;
            if (tg == 0) {
                // G band warp: rows [rbase,rbase+16), cols [16*band,128)
                #pragma unroll
                for (int ks = 0; ks < 2; ks++) {
                    const int g = 2 * ks + (l >> 4);
                    uint32_t af[4];
                    ldsm4(af, frag_addr(bA, rbase + (l & 15), g));
                    #pragma unroll
                    for (int p = 0; p < 8; p++) {
                        if (p >= band) {
                            uint32_t bb[4];
                            ldsm4(bb, frag_addr(bA, 16 * p + (l & 15), g));
                            mma16816(acc[2 * p],     af, bb[0], bb[2]);
                            mma16816(acc[2 * p + 1], af, bb[1], bb[3]);
                        }
                    }
                }
            } else {
                // A warp: 64x32 tile
                const uint32_t bOp = baseB0 + (uint32_t)buf * 8192;
                #pragma unroll
                for (int ks = 0; ks < 2; ks++) {
                    const int g = 2 * ks + (l >> 4);
                    uint32_t af[4][4];
                    #pragma unroll
                    for (int mt = 0; mt < 4; mt++)
                        ldsm4(af[mt], frag_addr(bA, mb + 16 * mt + (l & 15), g));
                    uint32_t bb[2][4];
                    #pragma unroll
                    for (int p = 0; p < 2; p++)
                        ldsm4(bb[p], frag_addr(bOp, nb + 16 * p + (l & 15), g));
                    #pragma unroll
                    for (int mt = 0; mt < 4; mt++)
                        #pragma unroll
                        for (int nt = 0; nt < 4; nt++)
                            mma16816(acc[mt * 4 + nt], af[mt],
                                     bb[nt >> 1][nt & 1], bb[nt >> 1][2 + (nt & 1)]);
                }
            }
        }

        // ---- convert + store chunk c+1 into nbuf ----
        if (has_next) {
            #pragma unroll
            for (int j = 0; j < 2; j++) {
                const int sq = sq0 + 8 * j;
                float p00 = phi_f(kp[2 * j].x),     p01 = phi_f(kp[2 * j].y);
                float p10 = phi_f(kp[2 * j + 1].x), p11 = phi_f(kp[2 * j + 1].y);
                smA[nbuf][stoff(2 * d2, sq)]     = packh2(p10, p00);
                smA[nbuf][stoff(2 * d2 + 1, sq)] = packh2(p11, p01);
                z0 += p00 + p10;
                z1 += p01 + p11;
                smB[nbuf][stoff(2 * d2, sq)]     = packh2(vp[2 * j + 1].x, vp[2 * j].x);
                smB[nbuf][stoff(2 * d2 + 1, sq)] = packh2(vp[2 * j + 1].y, vp[2 * j].y);
            }
        }
        __syncthreads();
    }

    // ---- epilogue ----
    const int r = l >> 2, cc = 2 * (l & 3);
    if (tg == 0) {
        float* dst = g_G + (size_t)(bh * NS + split) * 16384;
        const int row0 = rbase + r, row1 = rbase + r + 8;
        #pragma unroll
        for (int nt = 0; nt < 16; nt++) {
            if (nt >= ntlo) {
                const int col = 8 * nt + cc;
                *(float2*)(dst + (size_t)row0 * 128 + col) =
                    make_float2(acc[nt][0], acc[nt][1]);
                *(float2*)(dst + (size_t)row1 * 128 + col) =
                    make_float2(acc[nt][2], acc[nt][3]);
                if (nt >= ntlo + 2) {   // mirror strict-upper into lower
                    dst[(size_t)col * 128 + row0]       = acc[nt][0];
                    dst[(size_t)(col + 1) * 128 + row0] = acc[nt][1];
                    dst[(size_t)col * 128 + row1]       = acc[nt][2];
                    dst[(size_t)(col + 1) * 128 + row1] = acc[nt][3];
                }
            }
        }
    } else {
        float* dst = g_A + (size_t)(bh * NS + split) * 16384;
        #pragma unroll
        for (int mt = 0; mt < 4; mt++)
            #pragma unroll
            for (int nt = 0; nt < 4; nt++) {
                int row = mb + 16 * mt + r, col = nb + 8 * nt + cc;
                *(float2*)(dst + (size_t)row * 128 + col) =
                    make_float2(acc[mt * 4 + nt][0], acc[mt * 4 + nt][1]);
                *(float2*)(dst + (size_t)(row + 8) * 128 + col) =
                    make_float2(acc[mt * 4 + nt][2], acc[mt * 4 + nt][3]);
            }
    }

    // z partials
    *(float2*)(g_z + ((size_t)(bh * NS + split) * 8 + sq0) * 128 + 2 * d2) =
        make_float2(z0, z1);
}

// ---------------------------------------------------------------------------
// Phase 2: new_M = M + A - G*M ; new_z. grid (64, 4), 512 threads.
// M slice staged in smem; GT slabs; f32x2 FMA.
// ---------------------------------------------------------------------------
__device__ __forceinline__ u64 pk2(float x, float y) {
    u64 r; asm("mov.b64 %0,{%1,%2};" : "=l"(r) : "f"(x), "f"(y)); return r;
}
__device__ __forceinline__ void fma2(u64& c, u64 a, u64 b) {
    asm("fma.rn.f32x2 %0,%1,%2,%0;" : "+l"(c) : "l"(a), "l"(b));
}
__device__ __forceinline__ void add2(u64& c, u64 a) {
    asm("add.rn.f32x2 %0,%1,%0;" : "+l"(c) : "l"(a));
}

__global__ __launch_bounds__(512, 2)
void drp2_kernel(const float* __restrict__ M, const float* __restrict__ z,
                 float* __restrict__ out) {
    const int bh = blockIdx.x, q = blockIdx.y;
    __shared__ float GT[128 * 33];    // GT[i][kk], pad 33
    __shared__ float Msh[128 * 32];   // M[:, q*32 : q*32+32]

    const int tid = threadIdx.x;
    const int tx = tid & 7, ty = tid >> 3;    // 8 col-groups x 64 row-groups
    const int ra = ty * 2;                    // 2 rows
    const int cl = tx * 4;                    // local col (0..28)
    const int cb = q * 32 + cl;               // global col

    const float* Mp = M + (size_t)bh * 16384;
    const float* A0 = g_A + (size_t)bh * NS * 16384;
    const float* G0 = g_G + (size_t)bh * NS * 16384;

    // stage M slice
    for (int e = tid; e < 1024; e += 512) {
        int row = e >> 3, c4 = (e & 7) * 4;
        *(float4*)(Msh + row * 32 + c4) =
            __ldg((const float4*)(Mp + (size_t)row * 128 + q * 32 + c4));
    }
    __syncthreads();

    u64 acc[2][2];
    #pragma unroll
    for (int i = 0; i < 2; i++) {
        #pragma unroll
        for (int p = 0; p < 2; p++) {
            size_t o = (size_t)(ra + i) * 128 + cb + 2 * p;
            float2 m = *(const float2*)(Msh + (ra + i) * 32 + cl + 2 * p);
            u64 a = pk2(m.x, m.y);
            #pragma unroll
            for (int c = 0; c < NS; c++)
                add2(a, *(const u64*)(A0 + (size_t)c * 16384 + o));
            acc[i][p] = a;
        }
    }

    for (int ks = 0; ks < 128; ks += 32) {
        __syncthreads();
        for (int e = tid; e < 128 * 32; e += 512) {
            int kk = e & 31, i = e >> 5;
            float s = 0.f;
            #pragma unroll
            for (int c = 0; c < NS; c++)
                s += G0[(size_t)c * 16384 + (size_t)i * 128 + ks + kk];
            GT[i * 33 + kk] = s;
        }
        __syncthreads();

        #pragma unroll 8
        for (int kk = 0; kk < 32; kk++) {
            int k = ks + kk;
            float g0 = GT[(ra + 0) * 33 + kk];
            float g1 = GT[(ra + 1) * 33 + kk];
            float4 b = *(const float4*)(Msh + k * 32 + cl);
            u64 b0 = pk2(b.x, b.y), b1 = pk2(b.z, b.w);
            u64 pa0 = pk2(-g0, -g0), pa1 = pk2(-g1, -g1);
            fma2(acc[0][0], pa0, b0);
            fma2(acc[0][1], pa0, b1);
            fma2(acc[1][0], pa1, b0);
            fma2(acc[1][1], pa1, b1);
        }
    }

    float* outM = out + (size_t)bh * 16384;
    #pragma unroll
    for (int i = 0; i < 2; i++)
        #pragma unroll
        for (int p = 0; p < 2; p++)
            *(u64*)(outM + (size_t)(ra + i) * 128 + cb + 2 * p) = acc[i][p];

    if (q == 0 && tid < 128) {
        float s = z[(size_t)bh * 128 + tid];
        #pragma unroll
        for (int j = 0; j < NS * 8; j++)
            s += g_z[((size_t)bh * NS * 8 + j) * 128 + tid];
        out[(size_t)NBH * 16384 + (size_t)bh * 128 + tid] = s;
    }
}

extern "C" void kernel_launch(void* const* d_in, const int* in_sizes, int n_in,
                              void* d_out, int out_size) {
    const float* K = (const float*)d_in[0];
    const float* V = (const float*)d_in[1];
    const float* M = (const float*)d_in[2];
    const float* z = (const float*)d_in[3];
    float* out = (float*)d_out;

    drp1_kernel<<<dim3(NS, NBH), 512>>>(K, V);
    drp2_kernel<<<dim3(NBH, 4), 512>>>(M, z, out);
}